// round 3
// baseline (speedup 1.0000x reference)
#include <cuda_runtime.h>
#include <cuda_bf16.h>
#include <cstdint>

#define BB 8
#define NN 256
#define MM 16
#define DD 256

// bf16 centroids scratch: [B][N][D]
__device__ __nv_bfloat16 g_C[BB * NN * DD];
// per-(row, colhalf, warpN) LSE partials: [B*4096][4] (m, s)
__device__ float2 g_MS[BB * 4096 * 4];
// self term per row
__device__ float g_SELF[BB * 4096];

// ============================ helpers ============================
__device__ __forceinline__ uint32_t smem_u32(const void* p) {
    uint32_t a;
    asm("{ .reg .u64 t; cvta.to.shared.u64 t, %1; cvt.u32.u64 %0, t; }"
        : "=r"(a) : "l"(p));
    return a;
}
__device__ __forceinline__ float ex2f(float x) {
    float y; asm("ex2.approx.ftz.f32 %0, %1;" : "=f"(y) : "f"(x)); return y;
}
__device__ __forceinline__ float lg2f(float x) {
    float y; asm("lg2.approx.ftz.f32 %0, %1;" : "=f"(y) : "f"(x)); return y;
}
__device__ __forceinline__ void ldm_x4(uint32_t* r, uint32_t addr) {
    asm volatile("ldmatrix.sync.aligned.m8n8.x4.shared.b16 {%0,%1,%2,%3}, [%4];"
                 : "=r"(r[0]), "=r"(r[1]), "=r"(r[2]), "=r"(r[3])
                 : "r"(addr));
}
__device__ __forceinline__ void mma16816(float* d, const uint32_t* a,
                                         uint32_t b0, uint32_t b1) {
    asm volatile(
        "mma.sync.aligned.m16n8k16.row.col.f32.bf16.bf16.f32 "
        "{%0,%1,%2,%3}, {%4,%5,%6,%7}, {%8,%9}, {%0,%1,%2,%3};"
        : "+f"(d[0]), "+f"(d[1]), "+f"(d[2]), "+f"(d[3])
        : "r"(a[0]), "r"(a[1]), "r"(a[2]), "r"(a[3]), "r"(b0), "r"(b1));
}
__device__ __forceinline__ void cp_async16(uint32_t dst, const void* src) {
    asm volatile("cp.async.cg.shared.global [%0], [%1], 16;"
                 :: "r"(dst), "l"(src) : "memory");
}

// ============================ Kernel 1: centroids (float4) ============================
__global__ void centroid_kernel(const float* __restrict__ E) {
    int idx = blockIdx.x * blockDim.x + threadIdx.x;  // over B*N*D/4 = 131072
    int d4 = idx & 63;         // float4 within row
    int bn = idx >> 6;         // B*N group
    const float4* p = (const float4*)E + (size_t)bn * MM * 64 + d4;
    float4 s = make_float4(0.f, 0.f, 0.f, 0.f);
#pragma unroll
    for (int i = 0; i < MM; i++) {
        float4 v = p[(size_t)i * 64];
        s.x += v.x; s.y += v.y; s.z += v.z; s.w += v.w;
    }
    const float inv = 1.0f / MM;
    __nv_bfloat162 lo = __floats2bfloat162_rn(s.x * inv, s.y * inv);
    __nv_bfloat162 hi = __floats2bfloat162_rn(s.z * inv, s.w * inv);
    uint2 pk; pk.x = *(uint32_t*)&lo; pk.y = *(uint32_t*)&hi;
    *(uint2*)(g_C + (size_t)bn * DD + d4 * 4) = pk;
}

__global__ void zero_kernel(float* out) { out[0] = 0.0f; }

// ============================ Kernel 2: GEMM + partial LSE ============================
// smem: A 64x256 bf16 swizzled (32KB), B 128x256 bf16 swizzled (64KB), sqn 64 floats
static constexpr int SQN_OFF = 0;        // 64 floats
static constexpr int A_OFF   = 1024;     // 64 rows x 512 B = 32768
static constexpr int B_OFF   = 33792;    // 128 rows x 512 B = 65536
static constexpr int SMEM_TOTAL = 99328;

#define SWZ(row, un) ((uint32_t)(row) * 512u + ((((uint32_t)(un)) ^ ((uint32_t)(row) & 7u)) << 4))

__global__ void __launch_bounds__(256, 2) loss_kernel(
    const float* __restrict__ E,
    const float* __restrict__ wp,
    const float* __restrict__ bp)
{
    extern __shared__ char smem[];
    uint32_t sb = smem_u32(smem);
    int tid = threadIdx.x, wid = tid >> 5, L = tid & 31;
    int warpM = wid & 3, warpN = wid >> 2;   // 4x2 warp grid: warp tile 16 rows x 64 cols

    int bx    = blockIdx.x;        // 1024 = 8 batches * 64 rowtiles * 2 colhalves
    int batch = bx >> 7;
    int rt    = (bx >> 1) & 63;    // 64-row tile
    int ch    = bx & 1;            // 128-col half

    float w_s = *wp;
    float b_s = *bp;
    float* sqn = (float*)(smem + SQN_OFF);

    // ---- B tile via cp.async: C[batch][ch*128 ..][:] bf16, swizzled ----
    {
        const char* Cg = (const char*)(g_C + (size_t)batch * NN * DD + (size_t)ch * 128 * DD);
#pragma unroll
        for (int it = 0; it < 16; it++) {
            int u = it * 256 + tid;         // 4096 16B units: row*32 + un
            int row = u >> 5, un = u & 31;
            cp_async16(sb + B_OFF + SWZ(row, un), Cg + u * 16);
        }
        asm volatile("cp.async.commit_group;" ::: "memory");
    }

    // ---- A tile: 64 rows fp32 -> bf16, fp32 sq_norm per row ----
    {
        const float4* Eg = (const float4*)E + ((size_t)(batch * 4096 + rt * 64)) * 64;
#pragma unroll
        for (int it = 0; it < 8; it++) {
            int u = it * 256 + tid;         // 2048 16B-dst units; row = it*8+wid
            int row = u >> 5, un = u & 31;
            float4 v0 = Eg[u * 2];
            float4 v1 = Eg[u * 2 + 1];
            float ps = v0.x*v0.x + v0.y*v0.y + v0.z*v0.z + v0.w*v0.w
                     + v1.x*v1.x + v1.y*v1.y + v1.z*v1.z + v1.w*v1.w;
            ps += __shfl_xor_sync(0xFFFFFFFFu, ps, 16);
            ps += __shfl_xor_sync(0xFFFFFFFFu, ps, 8);
            ps += __shfl_xor_sync(0xFFFFFFFFu, ps, 4);
            ps += __shfl_xor_sync(0xFFFFFFFFu, ps, 2);
            ps += __shfl_xor_sync(0xFFFFFFFFu, ps, 1);
            if (L == 0) sqn[row] = ps;

            __nv_bfloat162 p0 = __floats2bfloat162_rn(v0.x, v0.y);
            __nv_bfloat162 p1 = __floats2bfloat162_rn(v0.z, v0.w);
            __nv_bfloat162 p2 = __floats2bfloat162_rn(v1.x, v1.y);
            __nv_bfloat162 p3 = __floats2bfloat162_rn(v1.z, v1.w);
            uint4 pk;
            pk.x = *(uint32_t*)&p0; pk.y = *(uint32_t*)&p1;
            pk.z = *(uint32_t*)&p2; pk.w = *(uint32_t*)&p3;
            *(uint4*)(smem + A_OFF + SWZ(row, un)) = pk;
        }
    }
    asm volatile("cp.async.wait_group 0;" ::: "memory");
    __syncthreads();

    // ---- per-lane ldmatrix addressing ----
    uint32_t arsk = (uint32_t)((L >> 4) ^ (L & 7));
    uint32_t aB   = sb + A_OFF + (uint32_t)(warpM * 16 + (L & 15)) * 512u;
    uint32_t brsk = (uint32_t)(((L >> 3) & 1) ^ (L & 7));
    uint32_t bB[4];
#pragma unroll
    for (int nb = 0; nb < 4; nb++)
        bB[nb] = sb + B_OFF +
                 (uint32_t)(warpN * 64 + nb * 16 + ((L >> 4) << 3) + (L & 7)) * 512u;

    float acc[8][4];
#pragma unroll
    for (int nf = 0; nf < 8; nf++)
#pragma unroll
        for (int q = 0; q < 4; q++) acc[nf][q] = 0.f;

    // ---- mainloop: K=256 in 16 steps of k16 ----
#pragma unroll 4
    for (int ks = 0; ks < 16; ks++) {
        uint32_t ku = (uint32_t)(ks * 2);
        uint32_t xa = ((ku ^ arsk) << 4);
        uint32_t xb = ((ku ^ brsk) << 4);
        uint32_t a[4];
        ldm_x4(a, aB + xa);
#pragma unroll
        for (int nb = 0; nb < 4; nb++) {
            uint32_t bf[4];
            ldm_x4(bf, bB[nb] + xb);
            mma16816(acc[2 * nb],     a, bf[0], bf[1]);
            mma16816(acc[2 * nb + 1], a, bf[2], bf[3]);
        }
    }

    // ---- epilogue: partial logsumexp over this CTA's 128 cols (per warp: 64) ----
    const float L2E = 1.44269504f;
    float wdiv = w_s * (1.0f / 15.0f);
    int dk   = rt * 4 + warpM;            // global diag col (same for warp's 16 rows)
    int cloc = dk - ch * 128;             // local col within CTA, valid if in [0,128)
    bool ownhalf = (cloc >= 0) && (cloc < 128) && ((cloc >> 6) == warpN);

#pragma unroll
    for (int rh = 0; rh < 2; rh++) {
        int row = warpM * 16 + (L >> 2) + rh * 8;   // local row in [0,64)
        int r_g = rt * 64 + row;                    // row within batch
        float sq = sqn[row];
        float m = -1e30f, sself = 0.f;
#pragma unroll
        for (int nf = 0; nf < 8; nf++) {
#pragma unroll
            for (int cq = 0; cq < 2; cq++) {
                float v = acc[nf][rh * 2 + cq];
                int col = warpN * 64 + nf * 8 + (L & 3) * 2 + cq;
                bool dg = (col == cloc);
                float xv = dg ? fmaf(wdiv, fmaf(16.f, v, -sq), b_s)
                              : fmaf(w_s, v, b_s);
                if (dg) sself = xv;
                m = fmaxf(m, xv);
            }
        }
        m = fmaxf(m, __shfl_xor_sync(0xFFFFFFFFu, m, 1));
        m = fmaxf(m, __shfl_xor_sync(0xFFFFFFFFu, m, 2));
        float s = 0.f;
#pragma unroll
        for (int nf = 0; nf < 8; nf++) {
#pragma unroll
            for (int cq = 0; cq < 2; cq++) {
                float v = acc[nf][rh * 2 + cq];
                int col = warpN * 64 + nf * 8 + (L & 3) * 2 + cq;
                float xv = (col == cloc) ? fmaf(wdiv, fmaf(16.f, v, -sq), b_s)
                                         : fmaf(w_s, v, b_s);
                s += ex2f((xv - m) * L2E);
            }
        }
        s += __shfl_xor_sync(0xFFFFFFFFu, s, 1);
        s += __shfl_xor_sync(0xFFFFFFFFu, s, 2);
        sself += __shfl_xor_sync(0xFFFFFFFFu, sself, 1);
        sself += __shfl_xor_sync(0xFFFFFFFFu, sself, 2);
        if ((L & 3) == 0) {
            int rid = (batch << 12) | r_g;
            g_MS[rid * 4 + ch * 2 + warpN] = make_float2(m, s);
            if (ownhalf) g_SELF[rid] = sself;
        }
    }
}

// ============================ Kernel 3: combine ============================
__global__ void combine_kernel(float* __restrict__ out) {
    int rid = blockIdx.x * blockDim.x + threadIdx.x;   // 32768 rows
    const float L2E = 1.44269504f, LN2 = 0.69314718f;
    float2 p0 = g_MS[rid * 4 + 0];
    float2 p1 = g_MS[rid * 4 + 1];
    float2 p2 = g_MS[rid * 4 + 2];
    float2 p3 = g_MS[rid * 4 + 3];
    float m = fmaxf(fmaxf(p0.x, p1.x), fmaxf(p2.x, p3.x));
    float s = p0.y * ex2f((p0.x - m) * L2E) + p1.y * ex2f((p1.x - m) * L2E)
            + p2.y * ex2f((p2.x - m) * L2E) + p3.y * ex2f((p3.x - m) * L2E);
    float contrib = m + lg2f(s) * LN2 - g_SELF[rid];

    contrib += __shfl_xor_sync(0xFFFFFFFFu, contrib, 16);
    contrib += __shfl_xor_sync(0xFFFFFFFFu, contrib, 8);
    contrib += __shfl_xor_sync(0xFFFFFFFFu, contrib, 4);
    contrib += __shfl_xor_sync(0xFFFFFFFFu, contrib, 2);
    contrib += __shfl_xor_sync(0xFFFFFFFFu, contrib, 1);
    __shared__ float red[8];
    int wid = threadIdx.x >> 5, L = threadIdx.x & 31;
    if (L == 0) red[wid] = contrib;
    __syncthreads();
    if (threadIdx.x == 0) {
        float t = 0.f;
#pragma unroll
        for (int w = 0; w < 8; w++) t += red[w];
        atomicAdd(out, t);
    }
}

// ============================ launch ============================
extern "C" void kernel_launch(void* const* d_in, const int* in_sizes, int n_in,
                              void* d_out, int out_size) {
    const float* E  = (const float*)d_in[0];
    const float* wp = (const float*)d_in[1];
    const float* bp = (const float*)d_in[2];
    float* out = (float*)d_out;

    centroid_kernel<<<(BB * NN * DD / 4) / 256, 256>>>(E);
    zero_kernel<<<1, 1>>>(out);

    cudaFuncSetAttribute(loss_kernel, cudaFuncAttributeMaxDynamicSharedMemorySize, SMEM_TOTAL);
    loss_kernel<<<BB * 64 * 2, 256, SMEM_TOTAL>>>(E, wp, bp);

    combine_kernel<<<BB * 4096 / 256, 256>>>(out);
}